// round 1
// baseline (speedup 1.0000x reference)
#include <cuda_runtime.h>

// Effective matrix, stored transposed+padded: d_Mt[g*128 + o], g,k in [0,128)
__device__ float d_Mt[128 * 128];

// ---- constants (match reference float32 values) ----
#define C0_     0.02795084971874737f   // sqrt(1/1280)
#define C1_     0.05103103630798288f   // sqrt(3/1152)
#define C2_     0.09882117688026186f   // sqrt(5/512)
#define INV_S3_ 0.57735026918962576f
#define INV_S5_ 0.44721359549995794f
#define RS0_    0.17677669529663687f   // 1/sqrt(32)
#define RS1_    0.25f                  // 1/sqrt(16)
#define RS2_    0.35355339059327373f   // 1/sqrt(8)

__device__ __forceinline__ void make_w3j(float C[3][3][5]) {
    const float s2 = 0.7071067811865476f;   // 1/sqrt(2)
    const float s6 = 0.4082482904638630f;   // 1/sqrt(6)
    const float i5 = 0.4472135954999579f;   // 1/sqrt(5)
#pragma unroll
    for (int i = 0; i < 3; i++)
#pragma unroll
        for (int j = 0; j < 3; j++)
#pragma unroll
            for (int k = 0; k < 5; k++) C[i][j][k] = 0.f;
    C[0][2][0] = s2;  C[2][0][0] = s2;
    C[0][1][1] = s2;  C[1][0][1] = s2;
    C[1][1][2] = 2.0f * s6;
    C[0][0][2] = -s6; C[2][2][2] = -s6;
    C[1][2][3] = s2;  C[2][1][3] = s2;
    C[2][2][4] = s2;  C[0][0][4] = -s2;
#pragma unroll
    for (int i = 0; i < 3; i++)
#pragma unroll
        for (int j = 0; j < 3; j++)
#pragma unroll
            for (int k = 0; k < 5; k++) C[i][j][k] *= i5;
}

// One thread per (o, g) entry of the effective 120x120 map (padded to 128x128).
__global__ void build_M(const float* __restrict__ field,
                        const float* __restrict__ w000,   // (32,32,32)
                        const float* __restrict__ w011,   // (32,16,16)
                        const float* __restrict__ w101,   // (16,32,16)
                        const float* __restrict__ w110,   // (16,16,32)
                        const float* __restrict__ w112,   // (16,16,8)
                        const float* __restrict__ w202,   // (8,32,8)
                        const float* __restrict__ w211,   // (8,16,16)
                        const float* __restrict__ wl0,    // (32,32)
                        const float* __restrict__ wl1,    // (16,16)
                        const float* __restrict__ wl2)    // (8,8)
{
    const int o = blockIdx.x;    // output index   0..127
    const int g = threadIdx.x;   // geometry index 0..127
    const float* f0 = field;        // [32]
    const float* f1 = field + 32;   // [16][3]

    float val = 0.f;
    if (o < 120 && g < 120) {
        float W[3][3][5];
        make_w3j(W);
        if (o < 32) {
            const int w = o;
            if (g < 32) {                       // out0 <- g0 : w_000 + wl0
                const int u = g;
                float s = 0.f;
#pragma unroll
                for (int v = 0; v < 32; v++) s += w000[u * 1024 + v * 32 + w] * f0[v];
                val = C0_ * s + wl0[u * 32 + w] * RS0_;
            } else if (g < 80) {                // out0 <- g1 : w_110
                const int u = (g - 32) / 3, i = (g - 32) % 3;
                float s = 0.f;
#pragma unroll
                for (int v = 0; v < 16; v++) s += w110[u * 512 + v * 32 + w] * f1[v * 3 + i];
                val = C0_ * INV_S3_ * s;
            }
        } else if (o < 80) {
            const int w = (o - 32) / 3, j = (o - 32) % 3;
            if (g < 32) {                       // out1 <- g0 : w_011
                const int u = g;
                float s = 0.f;
#pragma unroll
                for (int v = 0; v < 16; v++) s += w011[u * 256 + v * 16 + w] * f1[v * 3 + j];
                val = C1_ * INV_S3_ * s;
            } else if (g < 80) {                // out1 <- g1 : w_101 (diag in k) + wl1
                const int u = (g - 32) / 3, i = (g - 32) % 3;
                if (i == j) {
                    float s = 0.f;
#pragma unroll
                    for (int v = 0; v < 32; v++) s += w101[u * 512 + v * 16 + w] * f0[v];
                    val = C1_ * INV_S3_ * s + wl1[u * 16 + w] * RS1_;
                }
            } else {                            // out1 <- g2 : w_211 x W3J
                const int u = (g - 80) / 5, k = (g - 80) % 5;
                float s = 0.f;
#pragma unroll
                for (int i = 0; i < 3; i++) {
                    const float wj = W[i][j][k];
                    if (wj != 0.f) {
                        float t = 0.f;
#pragma unroll
                        for (int v = 0; v < 16; v++) t += w211[u * 256 + v * 16 + w] * f1[v * 3 + i];
                        s += wj * t;
                    }
                }
                val = C1_ * s;
            }
        } else {
            const int w = (o - 80) / 5, k = (o - 80) % 5;
            if (g >= 32 && g < 80) {            // out2 <- g1 : w_112 x W3J
                const int u = (g - 32) / 3, i = (g - 32) % 3;
                float s = 0.f;
#pragma unroll
                for (int j = 0; j < 3; j++) {
                    const float wj = W[i][j][k];
                    if (wj != 0.f) {
                        float t = 0.f;
#pragma unroll
                        for (int v = 0; v < 16; v++) t += w112[u * 128 + v * 8 + w] * f1[v * 3 + j];
                        s += wj * t;
                    }
                }
                val = C2_ * s;
            } else if (g >= 80) {               // out2 <- g2 : w_202 (diag in k) + wl2
                const int u = (g - 80) / 5, i2 = (g - 80) % 5;
                if (i2 == k) {
                    float s = 0.f;
#pragma unroll
                    for (int v = 0; v < 32; v++) s += w202[u * 256 + v * 8 + w] * f0[v];
                    val = C2_ * INV_S5_ * s + wl2[u * 8 + w] * RS2_;
                }
            }
        }
    }
    d_Mt[g * 128 + o] = val;
}

// ---------------------------------------------------------------------------
// GEMM: out[z, o] = sum_g G[z, g] * M[o, g]   (M read K-major from d_Mt)
// BM=128 atoms, BN=128 outputs (120 real), BK=40 (3 chunks), 256 thr, 8x8/thr
// ---------------------------------------------------------------------------
__global__ __launch_bounds__(256) void coupling_gemm(
    const float* __restrict__ G, float* __restrict__ out, int n)
{
    __shared__ float Gs[40][132];   // [k][atom], padded stride
    __shared__ float Ms[40][128];   // [k][o]

    const int tid = threadIdx.x;
    const int tx = tid & 15;        // output tile  (8 outs)
    const int ty = tid >> 4;        // atom tile    (8 atoms)
    const size_t z0 = (size_t)blockIdx.x * 128;

    float acc[8][8];
#pragma unroll
    for (int i = 0; i < 8; i++)
#pragma unroll
        for (int j = 0; j < 8; j++) acc[i][j] = 0.f;

    for (int kc = 0; kc < 3; ++kc) {
        const int k0 = kc * 40;

        // load M chunk: 40x128 floats, contiguous
        {
            const float4* src = (const float4*)(d_Mt + (size_t)k0 * 128);
            float4* dst = (float4*)(&Ms[0][0]);
#pragma unroll
            for (int t = tid; t < 1280; t += 256) dst[t] = src[t];
        }
        // load G chunk transposed: 128 atoms x 40 k
#pragma unroll
        for (int t = tid; t < 1280; t += 256) {
            const int a = t / 10, q = t % 10;
            const size_t row = z0 + a;
            float4 v = make_float4(0.f, 0.f, 0.f, 0.f);
            if (row < (size_t)n)
                v = *(const float4*)(G + row * 120 + k0 + q * 4);
            Gs[q * 4 + 0][a] = v.x;
            Gs[q * 4 + 1][a] = v.y;
            Gs[q * 4 + 2][a] = v.z;
            Gs[q * 4 + 3][a] = v.w;
        }
        __syncthreads();

#pragma unroll
        for (int k = 0; k < 40; ++k) {
            const float4 a0 = *(const float4*)&Gs[k][ty * 8];
            const float4 a1 = *(const float4*)&Gs[k][ty * 8 + 4];
            const float4 b0 = *(const float4*)&Ms[k][tx * 8];
            const float4 b1 = *(const float4*)&Ms[k][tx * 8 + 4];
            const float av[8] = {a0.x, a0.y, a0.z, a0.w, a1.x, a1.y, a1.z, a1.w};
            const float bv[8] = {b0.x, b0.y, b0.z, b0.w, b1.x, b1.y, b1.z, b1.w};
#pragma unroll
            for (int i = 0; i < 8; i++)
#pragma unroll
                for (int j = 0; j < 8; j++) acc[i][j] += av[i] * bv[j];
        }
        __syncthreads();
    }

    // store: cols tx*8..tx*8+7 (skip tx==15 -> padded cols 120..127)
    if (tx < 15) {
#pragma unroll
        for (int i = 0; i < 8; i++) {
            const size_t row = z0 + ty * 8 + i;
            if (row < (size_t)n) {
                float4 s0 = make_float4(acc[i][0], acc[i][1], acc[i][2], acc[i][3]);
                float4 s1 = make_float4(acc[i][4], acc[i][5], acc[i][6], acc[i][7]);
                *(float4*)(out + row * 120 + tx * 8)     = s0;
                *(float4*)(out + row * 120 + tx * 8 + 4) = s1;
            }
        }
    }
}

extern "C" void kernel_launch(void* const* d_in, const int* in_sizes, int n_in,
                              void* d_out, int out_size)
{
    const float* geom  = (const float*)d_in[0];
    const float* field = (const float*)d_in[1];
    const float* w000  = (const float*)d_in[2];
    const float* w011  = (const float*)d_in[3];
    const float* w101  = (const float*)d_in[4];
    const float* w110  = (const float*)d_in[5];
    const float* w112  = (const float*)d_in[6];
    const float* w202  = (const float*)d_in[7];
    const float* w211  = (const float*)d_in[8];
    const float* wl0   = (const float*)d_in[9];
    const float* wl1   = (const float*)d_in[10];
    const float* wl2   = (const float*)d_in[11];

    const int n = in_sizes[0] / 120;

    build_M<<<128, 128>>>(field, w000, w011, w101, w110, w112, w202, w211,
                          wl0, wl1, wl2);
    coupling_gemm<<<(n + 127) / 128, 256>>>(geom, (float*)d_out, n);
}

// round 2
// speedup vs baseline: 2.4664x; 2.4664x over previous
#include <cuda_runtime.h>
#include <cstdint>

// Effective matrix in tf32 mma-fragment order:
// d_Bf[kchunk][kstep][nfrag][idx][lane], 4*4*16*2*32 = 16384 floats
__device__ float d_Bf[16384];

// ---- constants (match reference float32 values) ----
#define C0_     0.02795084971874737f   // sqrt(1/1280)
#define C1_     0.05103103630798288f   // sqrt(3/1152)
#define C2_     0.09882117688026186f   // sqrt(5/512)
#define INV_S3_ 0.57735026918962576f
#define INV_S5_ 0.44721359549995794f
#define RS0_    0.17677669529663687f   // 1/sqrt(32)
#define RS1_    0.25f                  // 1/sqrt(16)
#define RS2_    0.35355339059327373f   // 1/sqrt(8)

__device__ __forceinline__ void make_w3j(float C[3][3][5]) {
    const float s2 = 0.7071067811865476f;   // 1/sqrt(2)
    const float s6 = 0.4082482904638630f;   // 1/sqrt(6)
    const float i5 = 0.4472135954999579f;   // 1/sqrt(5)
#pragma unroll
    for (int i = 0; i < 3; i++)
#pragma unroll
        for (int j = 0; j < 3; j++)
#pragma unroll
            for (int k = 0; k < 5; k++) C[i][j][k] = 0.f;
    C[0][2][0] = s2;  C[2][0][0] = s2;
    C[0][1][1] = s2;  C[1][0][1] = s2;
    C[1][1][2] = 2.0f * s6;
    C[0][0][2] = -s6; C[2][2][2] = -s6;
    C[1][2][3] = s2;  C[2][1][3] = s2;
    C[2][2][4] = s2;  C[0][0][4] = -s2;
#pragma unroll
    for (int i = 0; i < 3; i++)
#pragma unroll
        for (int j = 0; j < 3; j++)
#pragma unroll
            for (int k = 0; k < 5; k++) C[i][j][k] *= i5;
}

__device__ __forceinline__ uint32_t f2tf32(float v) {
    uint32_t t;
    asm("cvt.rna.tf32.f32 %0, %1;" : "=r"(t) : "f"(v));
    return t;
}

// One thread per (o, g) entry of the effective 120x120 map (padded to 128x128).
// o = output (N), g = geometry (K). Writes tf32 value into fragment layout.
__global__ void build_M(const float* __restrict__ field,
                        const float* __restrict__ w000,   // (32,32,32)
                        const float* __restrict__ w011,   // (32,16,16)
                        const float* __restrict__ w101,   // (16,32,16)
                        const float* __restrict__ w110,   // (16,16,32)
                        const float* __restrict__ w112,   // (16,16,8)
                        const float* __restrict__ w202,   // (8,32,8)
                        const float* __restrict__ w211,   // (8,16,16)
                        const float* __restrict__ wl0,    // (32,32)
                        const float* __restrict__ wl1,    // (16,16)
                        const float* __restrict__ wl2)    // (8,8)
{
    const int o = blockIdx.x;    // output index   0..127
    const int g = threadIdx.x;   // geometry index 0..127
    const float* f0 = field;        // [32]
    const float* f1 = field + 32;   // [16][3]

    float val = 0.f;
    if (o < 120 && g < 120) {
        float W[3][3][5];
        make_w3j(W);
        if (o < 32) {
            const int w = o;
            if (g < 32) {                       // out0 <- g0 : w_000 + wl0
                const int u = g;
                float s = 0.f;
#pragma unroll
                for (int v = 0; v < 32; v++) s += w000[u * 1024 + v * 32 + w] * f0[v];
                val = C0_ * s + wl0[u * 32 + w] * RS0_;
            } else if (g < 80) {                // out0 <- g1 : w_110
                const int u = (g - 32) / 3, i = (g - 32) % 3;
                float s = 0.f;
#pragma unroll
                for (int v = 0; v < 16; v++) s += w110[u * 512 + v * 32 + w] * f1[v * 3 + i];
                val = C0_ * INV_S3_ * s;
            }
        } else if (o < 80) {
            const int w = (o - 32) / 3, j = (o - 32) % 3;
            if (g < 32) {                       // out1 <- g0 : w_011
                const int u = g;
                float s = 0.f;
#pragma unroll
                for (int v = 0; v < 16; v++) s += w011[u * 256 + v * 16 + w] * f1[v * 3 + j];
                val = C1_ * INV_S3_ * s;
            } else if (g < 80) {                // out1 <- g1 : w_101 (diag in k) + wl1
                const int u = (g - 32) / 3, i = (g - 32) % 3;
                if (i == j) {
                    float s = 0.f;
#pragma unroll
                    for (int v = 0; v < 32; v++) s += w101[u * 512 + v * 16 + w] * f0[v];
                    val = C1_ * INV_S3_ * s + wl1[u * 16 + w] * RS1_;
                }
            } else {                            // out1 <- g2 : w_211 x W3J
                const int u = (g - 80) / 5, k = (g - 80) % 5;
                float s = 0.f;
#pragma unroll
                for (int i = 0; i < 3; i++) {
                    const float wj = W[i][j][k];
                    if (wj != 0.f) {
                        float t = 0.f;
#pragma unroll
                        for (int v = 0; v < 16; v++) t += w211[u * 256 + v * 16 + w] * f1[v * 3 + i];
                        s += wj * t;
                    }
                }
                val = C1_ * s;
            }
        } else {
            const int w = (o - 80) / 5, k = (o - 80) % 5;
            if (g >= 32 && g < 80) {            // out2 <- g1 : w_112 x W3J
                const int u = (g - 32) / 3, i = (g - 32) % 3;
                float s = 0.f;
#pragma unroll
                for (int j = 0; j < 3; j++) {
                    const float wj = W[i][j][k];
                    if (wj != 0.f) {
                        float t = 0.f;
#pragma unroll
                        for (int v = 0; v < 16; v++) t += w112[u * 128 + v * 8 + w] * f1[v * 3 + j];
                        s += wj * t;
                    }
                }
                val = C2_ * s;
            } else if (g >= 80) {               // out2 <- g2 : w_202 (diag in k) + wl2
                const int u = (g - 80) / 5, i2 = (g - 80) % 5;
                if (i2 == k) {
                    float s = 0.f;
#pragma unroll
                    for (int v = 0; v < 32; v++) s += w202[u * 256 + v * 8 + w] * f0[v];
                    val = C2_ * INV_S5_ * s + wl2[u * 8 + w] * RS2_;
                }
            }
        }
    }
    // fragment layout (m16n8k8 B frag, col-major B = [k][n]):
    //   b0: k = lane%4,     n = lane/4   (idx 0)
    //   b1: k = lane%4 + 4, n = lane/4   (idx 1)
    const int kchunk = g >> 5;
    const int kstep  = (g >> 3) & 3;
    const int idx    = (g >> 2) & 1;
    const int lane   = (o & 7) * 4 + (g & 3);
    d_Bf[((((kchunk * 4 + kstep) * 16 + (o >> 3)) * 2 + idx) * 32) + lane] =
        __uint_as_float(f2tf32(val));
}

// ---------------------------------------------------------------------------
// tf32 tensor-core GEMM:  out[z, o] = sum_g G[z, g] * M[o, g]
// CTA tile: 256 atoms x 128 outputs, K chunked by 32 (4 chunks).
// 8 warps as 4(m) x 2(n); warp tile 64x64 = 4 m-frags x 8 n-frags (m16n8k8).
// ---------------------------------------------------------------------------
__global__ __launch_bounds__(256, 1) void coupling_gemm_tf32(
    const float* __restrict__ G, float* __restrict__ out, int n)
{
    // As: [fr16 0..15][kstep 0..3][lane^kstep 0..31][idx 0..3] = 8192 f = 32KB
    __shared__ float As[8192];
    // Bs: [kstep][nfrag][idx][lane] = 4096 f = 16KB
    __shared__ float Bs[4096];

    const int tid   = threadIdx.x;
    const int lane  = tid & 31;
    const int warp  = tid >> 5;
    const int warpM = warp >> 1;   // 0..3
    const int warpN = warp & 1;    // 0..1
    const long long z0 = (long long)blockIdx.x * 256;

    float c[4][8][4];
#pragma unroll
    for (int mf = 0; mf < 4; mf++)
#pragma unroll
        for (int nf = 0; nf < 8; nf++)
#pragma unroll
            for (int q = 0; q < 4; q++) c[mf][nf][q] = 0.f;

    for (int kc = 0; kc < 4; kc++) {
        // ---- load A chunk: 256 rows x 32 k, convert to tf32, frag-scatter ----
#pragma unroll
        for (int i = 0; i < 8; i++) {
            const int f4  = i * 256 + tid;    // 0..2047
            const int row = f4 >> 3;          // 0..255
            const int q   = f4 & 7;           // 0..7
            const int kbase = kc * 32 + q * 4;
            const long long gr = z0 + row;
            float4 v = make_float4(0.f, 0.f, 0.f, 0.f);
            if (gr < (long long)n && kbase < 120)
                v = *(const float4*)(G + gr * 120 + kbase);
            const int fr16 = row >> 4;
            const int rr   = row & 15;
            const int kstep = q >> 1;
            float vv[4] = {v.x, v.y, v.z, v.w};
#pragma unroll
            for (int j = 0; j < 4; j++) {
                const int kk  = (q * 4 + j) & 7;
                const int l   = (((rr & 7) * 4 + (kk & 3)) ^ kstep);
                const int idx = ((rr >> 3) & 1) | (((kk >> 2) & 1) << 1);
                As[(((fr16 * 4 + kstep) * 32) + l) * 4 + idx] =
                    __uint_as_float(f2tf32(vv[j]));
            }
        }
        // ---- copy B chunk (already tf32 + frag-ordered): 1024 float4 ----
        {
            const float4* src = (const float4*)(d_Bf + kc * 4096);
            float4* dst = (float4*)Bs;
#pragma unroll
            for (int i = 0; i < 4; i++) dst[i * 256 + tid] = src[i * 256 + tid];
        }
        __syncthreads();

#pragma unroll
        for (int ks = 0; ks < 4; ks++) {
            // B frags (conflict-free LDS.32 x2 per frag)
            uint32_t b[8][2];
#pragma unroll
            for (int nf = 0; nf < 8; nf++) {
                const int base = ((ks * 16 + (warpN * 8 + nf)) * 2) * 32;
                b[nf][0] = __float_as_uint(Bs[base + lane]);
                b[nf][1] = __float_as_uint(Bs[base + 32 + lane]);
            }
            // A frags (conflict-free LDS.128)
            uint32_t a[4][4];
#pragma unroll
            for (int mf = 0; mf < 4; mf++) {
                const int fr16 = warpM * 4 + mf;
                const float4 aa = *(const float4*)
                    &As[(((fr16 * 4 + ks) * 32) + (lane ^ ks)) * 4];
                a[mf][0] = __float_as_uint(aa.x);
                a[mf][1] = __float_as_uint(aa.y);
                a[mf][2] = __float_as_uint(aa.z);
                a[mf][3] = __float_as_uint(aa.w);
            }
#pragma unroll
            for (int mf = 0; mf < 4; mf++) {
#pragma unroll
                for (int nf = 0; nf < 8; nf++) {
                    asm volatile(
                        "mma.sync.aligned.m16n8k8.row.col.f32.tf32.tf32.f32 "
                        "{%0,%1,%2,%3}, {%4,%5,%6,%7}, {%8,%9}, {%0,%1,%2,%3};"
                        : "+f"(c[mf][nf][0]), "+f"(c[mf][nf][1]),
                          "+f"(c[mf][nf][2]), "+f"(c[mf][nf][3])
                        : "r"(a[mf][0]), "r"(a[mf][1]), "r"(a[mf][2]), "r"(a[mf][3]),
                          "r"(b[nf][0]), "r"(b[nf][1]));
                }
            }
        }
        __syncthreads();
    }

    // ---- epilogue: c[mf][nf] -> out (N=120, skip padded frag 120..127) ----
#pragma unroll
    for (int mf = 0; mf < 4; mf++) {
        const int r0 = warpM * 64 + mf * 16 + (lane >> 2);
#pragma unroll
        for (int nf = 0; nf < 8; nf++) {
            const int col = warpN * 64 + nf * 8 + (lane & 3) * 2;
            if (col >= 120) continue;
            const long long row = z0 + r0;
            if (row < (long long)n)
                *(float2*)(out + row * 120 + col) =
                    make_float2(c[mf][nf][0], c[mf][nf][1]);
            if (row + 8 < (long long)n)
                *(float2*)(out + (row + 8) * 120 + col) =
                    make_float2(c[mf][nf][2], c[mf][nf][3]);
        }
    }
}

extern "C" void kernel_launch(void* const* d_in, const int* in_sizes, int n_in,
                              void* d_out, int out_size)
{
    const float* geom  = (const float*)d_in[0];
    const float* field = (const float*)d_in[1];
    const float* w000  = (const float*)d_in[2];
    const float* w011  = (const float*)d_in[3];
    const float* w101  = (const float*)d_in[4];
    const float* w110  = (const float*)d_in[5];
    const float* w112  = (const float*)d_in[6];
    const float* w202  = (const float*)d_in[7];
    const float* w211  = (const float*)d_in[8];
    const float* wl0   = (const float*)d_in[9];
    const float* wl1   = (const float*)d_in[10];
    const float* wl2   = (const float*)d_in[11];

    const int n = in_sizes[0] / 120;

    build_M<<<128, 128>>>(field, w000, w011, w101, w110, w112, w202, w211,
                          wl0, wl1, wl2);
    coupling_gemm_tf32<<<(n + 255) / 256, 256>>>(geom, (float*)d_out, n);
}

// round 4
// speedup vs baseline: 3.2212x; 1.3060x over previous
#include <cuda_runtime.h>
#include <cstdint>

// Effective matrix in tf32 mma-fragment order:
// d_Bf[kchunk][kstep][nfrag][idx][lane], 4*4*16*2*32 = 16384 floats
__device__ float d_Bf[16384];

// ---- constants (match reference float32 values) ----
#define C0_     0.02795084971874737f   // sqrt(1/1280)
#define C1_     0.05103103630798288f   // sqrt(3/1152)
#define C2_     0.09882117688026186f   // sqrt(5/512)
#define INV_S3_ 0.57735026918962576f
#define INV_S5_ 0.44721359549995794f
#define RS0_    0.17677669529663687f   // 1/sqrt(32)
#define RS1_    0.25f                  // 1/sqrt(16)
#define RS2_    0.35355339059327373f   // 1/sqrt(8)

__device__ __forceinline__ void make_w3j(float C[3][3][5]) {
    const float s2 = 0.7071067811865476f;
    const float s6 = 0.4082482904638630f;
    const float i5 = 0.4472135954999579f;
#pragma unroll
    for (int i = 0; i < 3; i++)
#pragma unroll
        for (int j = 0; j < 3; j++)
#pragma unroll
            for (int k = 0; k < 5; k++) C[i][j][k] = 0.f;
    C[0][2][0] = s2;  C[2][0][0] = s2;
    C[0][1][1] = s2;  C[1][0][1] = s2;
    C[1][1][2] = 2.0f * s6;
    C[0][0][2] = -s6; C[2][2][2] = -s6;
    C[1][2][3] = s2;  C[2][1][3] = s2;
    C[2][2][4] = s2;  C[0][0][4] = -s2;
#pragma unroll
    for (int i = 0; i < 3; i++)
#pragma unroll
        for (int j = 0; j < 3; j++)
#pragma unroll
            for (int k = 0; k < 5; k++) C[i][j][k] *= i5;
}

__device__ __forceinline__ uint32_t f2tf32(float v) {
    uint32_t t;
    asm("cvt.rna.tf32.f32 %0, %1;" : "=r"(t) : "f"(v));
    return t;
}

// One thread per (o, g) entry of the effective 120x120 map (padded 128x128).
__global__ void build_M(const float* __restrict__ field,
                        const float* __restrict__ w000,
                        const float* __restrict__ w011,
                        const float* __restrict__ w101,
                        const float* __restrict__ w110,
                        const float* __restrict__ w112,
                        const float* __restrict__ w202,
                        const float* __restrict__ w211,
                        const float* __restrict__ wl0,
                        const float* __restrict__ wl1,
                        const float* __restrict__ wl2)
{
    const int o = blockIdx.x;
    const int g = threadIdx.x;
    const float* f0 = field;
    const float* f1 = field + 32;

    float val = 0.f;
    if (o < 120 && g < 120) {
        float W[3][3][5];
        make_w3j(W);
        if (o < 32) {
            const int w = o;
            if (g < 32) {
                const int u = g;
                float s = 0.f;
#pragma unroll
                for (int v = 0; v < 32; v++) s += w000[u * 1024 + v * 32 + w] * f0[v];
                val = C0_ * s + wl0[u * 32 + w] * RS0_;
            } else if (g < 80) {
                const int u = (g - 32) / 3, i = (g - 32) % 3;
                float s = 0.f;
#pragma unroll
                for (int v = 0; v < 16; v++) s += w110[u * 512 + v * 32 + w] * f1[v * 3 + i];
                val = C0_ * INV_S3_ * s;
            }
        } else if (o < 80) {
            const int w = (o - 32) / 3, j = (o - 32) % 3;
            if (g < 32) {
                const int u = g;
                float s = 0.f;
#pragma unroll
                for (int v = 0; v < 16; v++) s += w011[u * 256 + v * 16 + w] * f1[v * 3 + j];
                val = C1_ * INV_S3_ * s;
            } else if (g < 80) {
                const int u = (g - 32) / 3, i = (g - 32) % 3;
                if (i == j) {
                    float s = 0.f;
#pragma unroll
                    for (int v = 0; v < 32; v++) s += w101[u * 512 + v * 16 + w] * f0[v];
                    val = C1_ * INV_S3_ * s + wl1[u * 16 + w] * RS1_;
                }
            } else {
                const int u = (g - 80) / 5, k = (g - 80) % 5;
                float s = 0.f;
#pragma unroll
                for (int i = 0; i < 3; i++) {
                    const float wj = W[i][j][k];
                    if (wj != 0.f) {
                        float t = 0.f;
#pragma unroll
                        for (int v = 0; v < 16; v++) t += w211[u * 256 + v * 16 + w] * f1[v * 3 + i];
                        s += wj * t;
                    }
                }
                val = C1_ * s;
            }
        } else {
            const int w = (o - 80) / 5, k = (o - 80) % 5;
            if (g >= 32 && g < 80) {
                const int u = (g - 32) / 3, i = (g - 32) % 3;
                float s = 0.f;
#pragma unroll
                for (int j = 0; j < 3; j++) {
                    const float wj = W[i][j][k];
                    if (wj != 0.f) {
                        float t = 0.f;
#pragma unroll
                        for (int v = 0; v < 16; v++) t += w112[u * 128 + v * 8 + w] * f1[v * 3 + j];
                        s += wj * t;
                    }
                }
                val = C2_ * s;
            } else if (g >= 80) {
                const int u = (g - 80) / 5, i2 = (g - 80) % 5;
                if (i2 == k) {
                    float s = 0.f;
#pragma unroll
                    for (int v = 0; v < 32; v++) s += w202[u * 256 + v * 8 + w] * f0[v];
                    val = C2_ * INV_S5_ * s + wl2[u * 8 + w] * RS2_;
                }
            }
        }
    }
    const int kchunk = g >> 5;
    const int kstep  = (g >> 3) & 3;
    const int idx    = (g >> 2) & 1;
    const int lane   = (o & 7) * 4 + (g & 3);
    d_Bf[((((kchunk * 4 + kstep) * 16 + (o >> 3)) * 2 + idx) * 32) + lane] =
        __uint_as_float(f2tf32(val));
}

// ---------------------------------------------------------------------------
// Pipelined tf32 GEMM: CTA 128 atoms x 128 outputs, BK=32 x 4 chunks.
// 8 warps: 4(M) x 2(N); warp tile 32x64 = 2 m-frags x 8 n-frags (m16n8k8).
// A: cp.async double-buffered raw rows, convert at LDS. B: resident in smem.
// ---------------------------------------------------------------------------
#define AS_STRIDE 36     // floats per row (128B data + 16B pad)
#define AS_BYTES  (128 * AS_STRIDE * 4)      // 18432 per stage
#define BS_FLOATS 16384                      // 64KB

extern __shared__ float smem_dyn[];

__device__ __forceinline__ void cp_async16(uint32_t dst, const void* src, int sz) {
    asm volatile("cp.async.cg.shared.global [%0], [%1], 16, %2;"
                 :: "r"(dst), "l"(src), "r"(sz));
}

__global__ __launch_bounds__(256, 2) void coupling_gemm_tf32(
    const float* __restrict__ G, float* __restrict__ out, int n)
{
    float* Bs = smem_dyn;                     // [16384]
    float* As = smem_dyn + BS_FLOATS;         // [2][128][36]
    const uint32_t as_base = (uint32_t)__cvta_generic_to_shared(As);

    const int tid   = threadIdx.x;
    const int lane  = tid & 31;
    const int warp  = tid >> 5;
    const int warpM = warp >> 1;   // 0..3 -> rows warpM*32
    const int warpN = warp & 1;    // 0..1 -> cols warpN*64
    const long long z0 = (long long)blockIdx.x * 128;

    // ---- load whole B once (frag-ordered, already tf32) ----
    {
        const float4* src = (const float4*)d_Bf;
        float4* dst = (float4*)Bs;
#pragma unroll
        for (int i = 0; i < 16; i++) dst[i * 256 + tid] = src[i * 256 + tid];
    }

    // ---- A chunk loader: 128 rows x 32 floats, 1024 x 16B, 4 per thread ----
    auto issue_A = [&](int kc, int buf) {
#pragma unroll
        for (int i = 0; i < 4; i++) {
            const int seg = i * 256 + tid;     // 0..1023
            const int row = seg >> 3;
            const int q   = seg & 7;
            const int kb  = kc * 32 + q * 4;
            const long long gr = z0 + row;
            const bool ok = (gr < (long long)n) && (kb <= 116);
            const uint32_t dst = as_base + buf * AS_BYTES + row * (AS_STRIDE * 4) + q * 16;
            // invalid -> src_size 0 => zero-fill, no global read
            cp_async16(dst, G + gr * 120 + kb, ok ? 16 : 0);
        }
        asm volatile("cp.async.commit_group;");
    };

    float c[2][8][4];
#pragma unroll
    for (int mf = 0; mf < 2; mf++)
#pragma unroll
        for (int nf = 0; nf < 8; nf++)
#pragma unroll
            for (int q = 0; q < 4; q++) c[mf][nf][q] = 0.f;

    issue_A(0, 0);

    for (int kc = 0; kc < 4; kc++) {
        const int buf = kc & 1;
        if (kc < 3) {
            issue_A(kc + 1, buf ^ 1);
            asm volatile("cp.async.wait_group 1;");
        } else {
            asm volatile("cp.async.wait_group 0;");
        }
        __syncthreads();

        const float* Ab = As + buf * (128 * AS_STRIDE);
#pragma unroll
        for (int ks = 0; ks < 4; ks++) {
            // B frags
            uint32_t b[8][2];
#pragma unroll
            for (int nf = 0; nf < 8; nf++) {
                const int base = ((kc * 4 + ks) * 16 + (warpN * 8 + nf)) * 64;
                b[nf][0] = __float_as_uint(Bs[base + lane]);
                b[nf][1] = __float_as_uint(Bs[base + 32 + lane]);
            }
            // A frags: raw f32 LDS + cvt to tf32
            uint32_t a[2][4];
#pragma unroll
            for (int mf = 0; mf < 2; mf++) {
                const int r0 = warpM * 32 + mf * 16 + (lane >> 2);
                const int kb = ks * 8 + (lane & 3);
                a[mf][0] = f2tf32(Ab[r0 * AS_STRIDE + kb]);
                a[mf][1] = f2tf32(Ab[(r0 + 8) * AS_STRIDE + kb]);
                a[mf][2] = f2tf32(Ab[r0 * AS_STRIDE + kb + 4]);
                a[mf][3] = f2tf32(Ab[(r0 + 8) * AS_STRIDE + kb + 4]);
            }
#pragma unroll
            for (int mf = 0; mf < 2; mf++) {
#pragma unroll
                for (int nf = 0; nf < 8; nf++) {
                    asm volatile(
                        "mma.sync.aligned.m16n8k8.row.col.f32.tf32.tf32.f32 "
                        "{%0,%1,%2,%3}, {%4,%5,%6,%7}, {%8,%9}, {%0,%1,%2,%3};"
                        : "+f"(c[mf][nf][0]), "+f"(c[mf][nf][1]),
                          "+f"(c[mf][nf][2]), "+f"(c[mf][nf][3])
                        : "r"(a[mf][0]), "r"(a[mf][1]), "r"(a[mf][2]), "r"(a[mf][3]),
                          "r"(b[nf][0]), "r"(b[nf][1]));
                }
            }
        }
        __syncthreads();
    }

    // ---- epilogue ----
#pragma unroll
    for (int mf = 0; mf < 2; mf++) {
        const int r0 = warpM * 32 + mf * 16 + (lane >> 2);
#pragma unroll
        for (int nf = 0; nf < 8; nf++) {
            const int col = warpN * 64 + nf * 8 + (lane & 3) * 2;
            if (col >= 120) continue;
            const long long row = z0 + r0;
            if (row < (long long)n)
                *(float2*)(out + row * 120 + col) =
                    make_float2(c[mf][nf][0], c[mf][nf][1]);
            if (row + 8 < (long long)n)
                *(float2*)(out + (row + 8) * 120 + col) =
                    make_float2(c[mf][nf][2], c[mf][nf][3]);
        }
    }
}

extern "C" void kernel_launch(void* const* d_in, const int* in_sizes, int n_in,
                              void* d_out, int out_size)
{
    const float* geom  = (const float*)d_in[0];
    const float* field = (const float*)d_in[1];
    const float* w000  = (const float*)d_in[2];
    const float* w011  = (const float*)d_in[3];
    const float* w101  = (const float*)d_in[4];
    const float* w110  = (const float*)d_in[5];
    const float* w112  = (const float*)d_in[6];
    const float* w202  = (const float*)d_in[7];
    const float* w211  = (const float*)d_in[8];
    const float* wl0   = (const float*)d_in[9];
    const float* wl1   = (const float*)d_in[10];
    const float* wl2   = (const float*)d_in[11];

    const int n = in_sizes[0] / 120;

    const int smem_bytes = BS_FLOATS * 4 + 2 * AS_BYTES;   // 65536 + 36864 = 102400
    cudaFuncSetAttribute(coupling_gemm_tf32,
                         cudaFuncAttributeMaxDynamicSharedMemorySize, smem_bytes);

    build_M<<<128, 128>>>(field, w000, w011, w101, w110, w112, w202, w211,
                          wl0, wl1, wl2);
    coupling_gemm_tf32<<<(n + 127) / 128, 256, smem_bytes>>>(geom, (float*)d_out, n);
}

// round 8
// speedup vs baseline: 3.8614x; 1.1987x over previous
#include <cuda_runtime.h>
#include <cstdint>

// Effective matrix, tf32, mma-fragment order, pairwise-packed:
// d_Bf[kchunk][kstep][nfrag][lane][idx], 4*4*16*32*2 = 16384 floats
__device__ float d_Bf[16384];

// ---- constants (match reference float32 values) ----
#define C0_     0.02795084971874737f   // sqrt(1/1280)
#define C1_     0.05103103630798288f   // sqrt(3/1152)
#define C2_     0.09882117688026186f   // sqrt(5/512)
#define INV_S3_ 0.57735026918962576f
#define INV_S5_ 0.44721359549995794f
#define RS0_    0.17677669529663687f   // 1/sqrt(32)
#define RS1_    0.25f                  // 1/sqrt(16)
#define RS2_    0.35355339059327373f   // 1/sqrt(8)

__device__ __forceinline__ void make_w3j(float C[3][3][5]) {
    const float s2 = 0.7071067811865476f;
    const float s6 = 0.4082482904638630f;
    const float i5 = 0.4472135954999579f;
#pragma unroll
    for (int i = 0; i < 3; i++)
#pragma unroll
        for (int j = 0; j < 3; j++)
#pragma unroll
            for (int k = 0; k < 5; k++) C[i][j][k] = 0.f;
    C[0][2][0] = s2;  C[2][0][0] = s2;
    C[0][1][1] = s2;  C[1][0][1] = s2;
    C[1][1][2] = 2.0f * s6;
    C[0][0][2] = -s6; C[2][2][2] = -s6;
    C[1][2][3] = s2;  C[2][1][3] = s2;
    C[2][2][4] = s2;  C[0][0][4] = -s2;
#pragma unroll
    for (int i = 0; i < 3; i++)
#pragma unroll
        for (int j = 0; j < 3; j++)
#pragma unroll
            for (int k = 0; k < 5; k++) C[i][j][k] *= i5;
}

__device__ __forceinline__ uint32_t f2tf32(float v) {
    uint32_t t;
    asm("cvt.rna.tf32.f32 %0, %1;" : "=r"(t) : "f"(v));
    return t;
}

// One thread per (o, g) entry of the effective 120x120 map (padded 128x128).
__global__ void build_M(const float* __restrict__ field,
                        const float* __restrict__ w000,
                        const float* __restrict__ w011,
                        const float* __restrict__ w101,
                        const float* __restrict__ w110,
                        const float* __restrict__ w112,
                        const float* __restrict__ w202,
                        const float* __restrict__ w211,
                        const float* __restrict__ wl0,
                        const float* __restrict__ wl1,
                        const float* __restrict__ wl2)
{
    const int o = blockIdx.x;
    const int g = threadIdx.x;
    const float* f0 = field;
    const float* f1 = field + 32;

    float val = 0.f;
    if (o < 120 && g < 120) {
        float W[3][3][5];
        make_w3j(W);
        if (o < 32) {
            const int w = o;
            if (g < 32) {
                const int u = g;
                float s = 0.f;
#pragma unroll
                for (int v = 0; v < 32; v++) s += w000[u * 1024 + v * 32 + w] * f0[v];
                val = C0_ * s + wl0[u * 32 + w] * RS0_;
            } else if (g < 80) {
                const int u = (g - 32) / 3, i = (g - 32) % 3;
                float s = 0.f;
#pragma unroll
                for (int v = 0; v < 16; v++) s += w110[u * 512 + v * 32 + w] * f1[v * 3 + i];
                val = C0_ * INV_S3_ * s;
            }
        } else if (o < 80) {
            const int w = (o - 32) / 3, j = (o - 32) % 3;
            if (g < 32) {
                const int u = g;
                float s = 0.f;
#pragma unroll
                for (int v = 0; v < 16; v++) s += w011[u * 256 + v * 16 + w] * f1[v * 3 + j];
                val = C1_ * INV_S3_ * s;
            } else if (g < 80) {
                const int u = (g - 32) / 3, i = (g - 32) % 3;
                if (i == j) {
                    float s = 0.f;
#pragma unroll
                    for (int v = 0; v < 32; v++) s += w101[u * 512 + v * 16 + w] * f0[v];
                    val = C1_ * INV_S3_ * s + wl1[u * 16 + w] * RS1_;
                }
            } else {
                const int u = (g - 80) / 5, k = (g - 80) % 5;
                float s = 0.f;
#pragma unroll
                for (int i = 0; i < 3; i++) {
                    const float wj = W[i][j][k];
                    if (wj != 0.f) {
                        float t = 0.f;
#pragma unroll
                        for (int v = 0; v < 16; v++) t += w211[u * 256 + v * 16 + w] * f1[v * 3 + i];
                        s += wj * t;
                    }
                }
                val = C1_ * s;
            }
        } else {
            const int w = (o - 80) / 5, k = (o - 80) % 5;
            if (g >= 32 && g < 80) {
                const int u = (g - 32) / 3, i = (g - 32) % 3;
                float s = 0.f;
#pragma unroll
                for (int j = 0; j < 3; j++) {
                    const float wj = W[i][j][k];
                    if (wj != 0.f) {
                        float t = 0.f;
#pragma unroll
                        for (int v = 0; v < 16; v++) t += w112[u * 128 + v * 8 + w] * f1[v * 3 + j];
                        s += wj * t;
                    }
                }
                val = C2_ * s;
            } else if (g >= 80) {
                const int u = (g - 80) / 5, i2 = (g - 80) % 5;
                if (i2 == k) {
                    float s = 0.f;
#pragma unroll
                    for (int v = 0; v < 32; v++) s += w202[u * 256 + v * 8 + w] * f0[v];
                    val = C2_ * INV_S5_ * s + wl2[u * 8 + w] * RS2_;
                }
            }
        }
    }
    const int kchunk = g >> 5;
    const int kstep  = (g >> 3) & 3;
    const int idx    = (g >> 2) & 1;
    const int lane   = (o & 7) * 4 + (g & 3);
    const int nfrag  = o >> 3;
    // pairwise-packed: [kchunk][kstep][nfrag][lane][idx]
    d_Bf[(((kchunk * 4 + kstep) * 16 + nfrag) * 32 + lane) * 2 + idx] =
        __uint_as_float(f2tf32(val));
}

// ---------------------------------------------------------------------------
// tf32 GEMM: CTA 128 atoms x 128 outputs, BK=32 x 4 chunks.
// 8 warps: 4(M) x 2(N); warp tile 32x64 = 2 m-frags x 8 n-frags (m16n8k8).
// A: 4-deep cp.async prefetch (all chunks at start), XOR-swizzled raw rows.
// B: 2-stage cp.async staging from L2-resident d_Bf, LDS.64 frag reads.
// ---------------------------------------------------------------------------
#define A_STAGE_F 4096                 // 128 rows * 32 floats = 16KB/stage
#define B_STAGE_F 4096                 // 16KB/stage

extern __shared__ float smem_dyn[];

__device__ __forceinline__ void cp_async16(uint32_t dst, const void* src, int sz) {
    asm volatile("cp.async.cg.shared.global [%0], [%1], 16, %2;"
                 :: "r"(dst), "l"(src), "r"(sz));
}

__global__ __launch_bounds__(256, 2) void coupling_gemm_tf32(
    const float* __restrict__ G, float* __restrict__ out, int n)
{
    float* Bs = smem_dyn;                      // [2][4096]
    float* As = smem_dyn + 2 * B_STAGE_F;      // [4][4096]
    const uint32_t as_base = (uint32_t)__cvta_generic_to_shared(As);
    const uint32_t bs_base = (uint32_t)__cvta_generic_to_shared(Bs);

    const int tid   = threadIdx.x;
    const int lane  = tid & 31;
    const int warp  = tid >> 5;
    const int warpM = warp >> 1;   // 0..3 -> rows warpM*32
    const int warpN = warp & 1;    // 0..1 -> cols warpN*64
    const long long z0 = (long long)blockIdx.x * 128;

    // A loader: chunk kc -> stage kc. XOR swizzle on 16B granule.
    auto issue_A = [&](int kc) {
#pragma unroll
        for (int i = 0; i < 4; i++) {
            const int seg = i * 256 + tid;     // 0..1023
            const int row = seg >> 3;          // 0..127
            const int q   = seg & 7;           // 16B granule within row
            const int kb  = kc * 32 + q * 4;
            const long long gr = z0 + row;
            const bool ok = (gr < (long long)n) && (kb <= 116);
            const uint32_t dst = as_base + kc * (A_STAGE_F * 4)
                               + row * 128 + ((q ^ (row & 7)) << 4);
            cp_async16(dst, G + gr * 120 + kb, ok ? 16 : 0);
        }
    };
    // B loader: chunk kc -> buf (kc&1), contiguous copy from d_Bf.
    auto issue_B = [&](int kc) {
#pragma unroll
        for (int i = 0; i < 4; i++) {
            const int seg = i * 256 + tid;     // 0..1023
            const uint32_t dst = bs_base + (kc & 1) * (B_STAGE_F * 4) + seg * 16;
            cp_async16(dst, d_Bf + kc * B_STAGE_F + seg * 4, 16);
        }
    };

    // group 0: A0 + B0 ; group 1: A1 + B1 + A2 + A3  (A fully prefetched)
    issue_A(0); issue_B(0);
    asm volatile("cp.async.commit_group;");
    issue_A(1); issue_B(1); issue_A(2); issue_A(3);
    asm volatile("cp.async.commit_group;");

    float c[2][8][4];
#pragma unroll
    for (int mf = 0; mf < 2; mf++)
#pragma unroll
        for (int nf = 0; nf < 8; nf++)
#pragma unroll
            for (int q = 0; q < 4; q++) c[mf][nf][q] = 0.f;

#pragma unroll
    for (int kc = 0; kc < 4; kc++) {
        if (kc < 3) asm volatile("cp.async.wait_group 1;");
        else        asm volatile("cp.async.wait_group 0;");
        __syncthreads();

        const float* Ab = As + kc * A_STAGE_F;
        const float* Bb = Bs + (kc & 1) * B_STAGE_F;
#pragma unroll
        for (int ks = 0; ks < 4; ks++) {
            // B frags: one LDS.64 each
            uint32_t b[8][2];
#pragma unroll
            for (int nf = 0; nf < 8; nf++) {
                const float2 bv = *(const float2*)
                    &Bb[((ks * 16 + (warpN * 8 + nf)) * 32 + lane) * 2];
                b[nf][0] = __float_as_uint(bv.x);
                b[nf][1] = __float_as_uint(bv.y);
            }
            // A frags: raw f32 LDS (XOR-swizzled) + cvt to tf32
            uint32_t a[2][4];
#pragma unroll
            for (int mf = 0; mf < 2; mf++) {
                const int r0 = warpM * 32 + mf * 16 + (lane >> 2);
                const int r1 = r0 + 8;
                const int c0 = (lane & 3);
                const int q0 = ks * 2, q1 = ks * 2 + 1;
                a[mf][0] = f2tf32(Ab[r0 * 32 + ((q0 ^ (r0 & 7)) << 2) + c0]);
                a[mf][1] = f2tf32(Ab[r1 * 32 + ((q0 ^ (r1 & 7)) << 2) + c0]);
                a[mf][2] = f2tf32(Ab[r0 * 32 + ((q1 ^ (r0 & 7)) << 2) + c0]);
                a[mf][3] = f2tf32(Ab[r1 * 32 + ((q1 ^ (r1 & 7)) << 2) + c0]);
            }
#pragma unroll
            for (int mf = 0; mf < 2; mf++) {
#pragma unroll
                for (int nf = 0; nf < 8; nf++) {
                    asm volatile(
                        "mma.sync.aligned.m16n8k8.row.col.f32.tf32.tf32.f32 "
                        "{%0,%1,%2,%3}, {%4,%5,%6,%7}, {%8,%9}, {%0,%1,%2,%3};"
                        : "+f"(c[mf][nf][0]), "+f"(c[mf][nf][1]),
                          "+f"(c[mf][nf][2]), "+f"(c[mf][nf][3])
                        : "r"(a[mf][0]), "r"(a[mf][1]), "r"(a[mf][2]), "r"(a[mf][3]),
                          "r"(b[nf][0]), "r"(b[nf][1]));
                }
            }
        }
        __syncthreads();
        if (kc < 2) {                  // refill B buf (kc&1) with chunk kc+2
            issue_B(kc + 2);
            asm volatile("cp.async.commit_group;");
        }
    }

    // ---- epilogue ----
#pragma unroll
    for (int mf = 0; mf < 2; mf++) {
        const int r0 = warpM * 32 + mf * 16 + (lane >> 2);
#pragma unroll
        for (int nf = 0; nf < 8; nf++) {
            const int col = warpN * 64 + nf * 8 + (lane & 3) * 2;
            if (col >= 120) continue;
            const long long row = z0 + r0;
            if (row < (long long)n)
                *(float2*)(out + row * 120 + col) =
                    make_float2(c[mf][nf][0], c[mf][nf][1]);
            if (row + 8 < (long long)n)
                *(float2*)(out + (row + 8) * 120 + col) =
                    make_float2(c[mf][nf][2], c[mf][nf][3]);
        }
    }
}

extern "C" void kernel_launch(void* const* d_in, const int* in_sizes, int n_in,
                              void* d_out, int out_size)
{
    const float* geom  = (const float*)d_in[0];
    const float* field = (const float*)d_in[1];
    const float* w000  = (const float*)d_in[2];
    const float* w011  = (const float*)d_in[3];
    const float* w101  = (const float*)d_in[4];
    const float* w110  = (const float*)d_in[5];
    const float* w112  = (const float*)d_in[6];
    const float* w202  = (const float*)d_in[7];
    const float* w211  = (const float*)d_in[8];
    const float* wl0   = (const float*)d_in[9];
    const float* wl1   = (const float*)d_in[10];
    const float* wl2   = (const float*)d_in[11];

    const int n = in_sizes[0] / 120;

    const int smem_bytes = (2 * B_STAGE_F + 4 * A_STAGE_F) * 4;   // 96KB
    cudaFuncSetAttribute(coupling_gemm_tf32,
                         cudaFuncAttributeMaxDynamicSharedMemorySize, smem_bytes);

    build_M<<<128, 128>>>(field, w000, w011, w101, w110, w112, w202, w211,
                          wl0, wl1, wl2);
    coupling_gemm_tf32<<<(n + 127) / 128, 256, smem_bytes>>>(geom, (float*)d_out, n);
}